// round 3
// baseline (speedup 1.0000x reference)
#include <cuda_runtime.h>
#include <cuda_bf16.h>

#define NCH 128
#define HEADS 4
#define NMAX 50000
#define EMAX 600000
#define TOTMAX (EMAX + NMAX)
#define BN_EPS 1e-5f

// ---------------- device scratch (no allocs allowed) ----------------
__device__ float g_H[NMAX * NCH];     // per-layer GEMM output (gather source)
__device__ float g_A[NMAX * NCH];     // activation ping
__device__ float g_B[NMAX * NCH];     // activation pong (also residual identity)
__device__ float g_AGG[NMAX * NCH];   // pre-BN aggregation output
__device__ float g_AS[NMAX * HEADS];
__device__ float g_AD[NMAX * HEADS];
__device__ int   g_deg[NMAX];
__device__ int   g_rowptr[NMAX + 1];
__device__ int   g_cursor[NMAX];
__device__ int   g_csrsrc[TOTMAX];
__device__ float g_bnsum[NCH];
__device__ float g_bnsq[NCH];
__device__ float g_scale[NCH];
__device__ float g_shift[NCH];

__device__ __forceinline__ float lrelu(float x) { return x >= 0.f ? x : 0.2f * x; }

// Blackwell packed fp32 FMA: 2 FMAs per instruction (scalar FFMA is rt=2 per
// SMSP on sm_10x; f32x2 doubles effective fp32 throughput).
__device__ __forceinline__ float2 ffma2(float2 a, float2 b, float2 c) {
    float2 d;
    asm("fma.rn.f32x2 %0, %1, %2, %3;"
        : "=l"(*reinterpret_cast<unsigned long long*>(&d))
        : "l"(*reinterpret_cast<unsigned long long*>(&a)),
          "l"(*reinterpret_cast<unsigned long long*>(&b)),
          "l"(*reinterpret_cast<unsigned long long*>(&c)));
    return d;
}

// ---------------- CSR build ----------------
__global__ void k_deginit(int N) {
    int i = blockIdx.x * blockDim.x + threadIdx.x;
    if (i < N) g_deg[i] = 1;  // self-loop
}

__global__ void k_hist(const int* __restrict__ ei, int E) {
    int i = blockIdx.x * blockDim.x + threadIdx.x;
    if (i < E) atomicAdd(&g_deg[ei[E + i]], 1);
}

// one-block exclusive scan of g_deg -> g_rowptr (+ cursor copy)
__global__ void k_scan(int N) {
    __shared__ int ssum[1024];
    int t = threadIdx.x;
    int per = (N + 1023) / 1024;
    int beg = t * per;
    int end = min(beg + per, N);
    if (beg > N) beg = N;
    int local = 0;
    for (int i = beg; i < end; i++) local += g_deg[i];
    ssum[t] = local;
    __syncthreads();
    for (int off = 1; off < 1024; off <<= 1) {
        int add = (t >= off) ? ssum[t - off] : 0;
        __syncthreads();
        ssum[t] += add;
        __syncthreads();
    }
    int run = ssum[t] - local;  // exclusive prefix
    for (int i = beg; i < end; i++) {
        g_rowptr[i] = run;
        g_cursor[i] = run;
        run += g_deg[i];
    }
    if (t == 1023) g_rowptr[N] = run;
}

__global__ void k_scatter(const int* __restrict__ ei, int E, int N) {
    int i = blockIdx.x * blockDim.x + threadIdx.x;
    if (i < E) {
        int d = ei[E + i];
        int pos = atomicAdd(&g_cursor[d], 1);
        g_csrsrc[pos] = ei[i];
    } else if (i < E + N) {
        int n = i - E;
        int pos = atomicAdd(&g_cursor[n], 1);
        g_csrsrc[pos] = n;
    }
}

// ---------------- GEMM: H = X @ W, plus per-node attention logits ----------------
// 128x128 output tile per block, 256 threads, each thread 8x8 microtile with
// packed f32x2 accumulation. W and X tiles staged in dynamic smem (padded rows).
#define SROW 132
#define GEMM_SMEM ((2 * 128 * SROW + 128 + 128 + 512 + 512) * (int)sizeof(float))

__global__ void __launch_bounds__(256, 1)
k_gemm(const float* __restrict__ X, const float* __restrict__ W,
       const float* __restrict__ atts, const float* __restrict__ attd, int N) {
    extern __shared__ float sm[];
    float* sX   = sm;
    float* sW   = sm + 128 * SROW;
    float* satS = sW + 128 * SROW;
    float* satD = satS + 128;
    float* sAS  = satD + 128;
    float* sAD  = sAS + 512;

    const int t = threadIdx.x;
    if (blockIdx.x == 0 && t < 128) { g_bnsum[t] = 0.f; g_bnsq[t] = 0.f; }
    if (t < 128) { satS[t] = atts[t]; satD[t] = attd[t]; }
    for (int i = t; i < 512; i += 256) { sAS[i] = 0.f; sAD[i] = 0.f; }

    const int row0 = blockIdx.x * 128;
    for (int i = t * 4; i < 128 * 128; i += 1024) {
        int r = i >> 7, c = i & 127;
        *(float4*)&sW[r * SROW + c] = *(const float4*)&W[i];
        int gr = row0 + r;
        float4 xv = (gr < N) ? *(const float4*)&X[gr * NCH + c] : make_float4(0, 0, 0, 0);
        *(float4*)&sX[r * SROW + c] = xv;
    }
    __syncthreads();

    const int tx = t & 15, ty = t >> 4;
    const int c0 = tx * 8, r0 = ty * 8;

    float2 acc[8][4];
#pragma unroll
    for (int r = 0; r < 8; r++)
#pragma unroll
        for (int j = 0; j < 4; j++) acc[r][j] = make_float2(0.f, 0.f);

    for (int k = 0; k < 128; k += 4) {
        float4 xv[8];
#pragma unroll
        for (int r = 0; r < 8; r++) xv[r] = *(const float4*)&sX[(r0 + r) * SROW + k];
#pragma unroll
        for (int kk = 0; kk < 4; kk++) {
            const float* wrow = &sW[(k + kk) * SROW + c0];
            float4 wa = *(const float4*)(wrow);
            float4 wb = *(const float4*)(wrow + 4);
            float2 w0 = make_float2(wa.x, wa.y), w1 = make_float2(wa.z, wa.w);
            float2 w2 = make_float2(wb.x, wb.y), w3 = make_float2(wb.z, wb.w);
#pragma unroll
            for (int r = 0; r < 8; r++) {
                float xs = (kk == 0) ? xv[r].x : (kk == 1) ? xv[r].y : (kk == 2) ? xv[r].z : xv[r].w;
                float2 xx = make_float2(xs, xs);
                acc[r][0] = ffma2(xx, w0, acc[r][0]);
                acc[r][1] = ffma2(xx, w1, acc[r][1]);
                acc[r][2] = ffma2(xx, w2, acc[r][2]);
                acc[r][3] = ffma2(xx, w3, acc[r][3]);
            }
        }
    }

    // epilogue: store H tile + partial attention dots (8 cols lie in one head)
    const int hd = c0 >> 5;
#pragma unroll
    for (int r = 0; r < 8; r++) {
        float ps = 0.f, pd = 0.f;
#pragma unroll
        for (int j = 0; j < 4; j++) {
            int c = c0 + j * 2;
            ps = fmaf(acc[r][j].x, satS[c], fmaf(acc[r][j].y, satS[c + 1], ps));
            pd = fmaf(acc[r][j].x, satD[c], fmaf(acc[r][j].y, satD[c + 1], pd));
        }
        atomicAdd(&sAS[(r0 + r) * 4 + hd], ps);
        atomicAdd(&sAD[(r0 + r) * 4 + hd], pd);
        int gr = row0 + r0 + r;
        if (gr < N) {
            *(float4*)&g_H[gr * NCH + c0] =
                make_float4(acc[r][0].x, acc[r][0].y, acc[r][1].x, acc[r][1].y);
            *(float4*)&g_H[gr * NCH + c0 + 4] =
                make_float4(acc[r][2].x, acc[r][2].y, acc[r][3].x, acc[r][3].y);
        }
    }
    __syncthreads();
    for (int i = t; i < 512; i += 256) {
        int gr = row0 + (i >> 2);
        if (gr < N) {
            g_AS[gr * 4 + (i & 3)] = sAS[i];
            g_AD[gr * 4 + (i & 3)] = sAD[i];
        }
    }
}

// ---------------- aggregation: warp per dst node, softmax fused, no atomics ----------------
__global__ void __launch_bounds__(256)
k_agg(const float* __restrict__ bias, int N) {
    __shared__ float sSum[128], sSq[128];
    int t = threadIdx.x;
    if (t < 128) { sSum[t] = 0.f; sSq[t] = 0.f; }
    __syncthreads();

    int node = (blockIdx.x * 256 + t) >> 5;
    int lane = t & 31;
    if (node < N) {
        int beg = g_rowptr[node], end = g_rowptr[node + 1];
        float4 ad4 = *(const float4*)&g_AD[node * 4];

        // online softmax (per lane over strided edges, then butterfly merge)
        float m0 = -1e30f, m1 = -1e30f, m2 = -1e30f, m3 = -1e30f;
        float s0 = 0.f, s1 = 0.f, s2 = 0.f, s3 = 0.f;
        for (int j = beg + lane; j < end; j += 32) {
            int s = g_csrsrc[j];
            float4 a = *(const float4*)&g_AS[s * 4];
            float e0 = lrelu(a.x + ad4.x), e1 = lrelu(a.y + ad4.y);
            float e2 = lrelu(a.z + ad4.z), e3 = lrelu(a.w + ad4.w);
            float n0 = fmaxf(m0, e0); s0 = s0 * __expf(m0 - n0) + __expf(e0 - n0); m0 = n0;
            float n1 = fmaxf(m1, e1); s1 = s1 * __expf(m1 - n1) + __expf(e1 - n1); m1 = n1;
            float n2 = fmaxf(m2, e2); s2 = s2 * __expf(m2 - n2) + __expf(e2 - n2); m2 = n2;
            float n3 = fmaxf(m3, e3); s3 = s3 * __expf(m3 - n3) + __expf(e3 - n3); m3 = n3;
        }
#pragma unroll
        for (int off = 16; off; off >>= 1) {
            float om, os, n;
            om = __shfl_xor_sync(~0u, m0, off); os = __shfl_xor_sync(~0u, s0, off);
            n = fmaxf(m0, om); s0 = s0 * __expf(m0 - n) + os * __expf(om - n); m0 = n;
            om = __shfl_xor_sync(~0u, m1, off); os = __shfl_xor_sync(~0u, s1, off);
            n = fmaxf(m1, om); s1 = s1 * __expf(m1 - n) + os * __expf(om - n); m1 = n;
            om = __shfl_xor_sync(~0u, m2, off); os = __shfl_xor_sync(~0u, s2, off);
            n = fmaxf(m2, om); s2 = s2 * __expf(m2 - n) + os * __expf(om - n); m2 = n;
            om = __shfl_xor_sync(~0u, m3, off); os = __shfl_xor_sync(~0u, s3, off);
            n = fmaxf(m3, om); s3 = s3 * __expf(m3 - n) + os * __expf(om - n); m3 = n;
        }
        float i0 = __fdividef(1.f, s0), i1 = __fdividef(1.f, s1);
        float i2 = __fdividef(1.f, s2), i3 = __fdividef(1.f, s3);

        int hd = lane >> 3;
        float mh  = hd == 0 ? m0 : hd == 1 ? m1 : hd == 2 ? m2 : m3;
        float ih  = hd == 0 ? i0 : hd == 1 ? i1 : hd == 2 ? i2 : i3;
        float adv = hd == 0 ? ad4.x : hd == 1 ? ad4.y : hd == 2 ? ad4.z : ad4.w;
        int cb = lane * 4;

        float4 acc = make_float4(0.f, 0.f, 0.f, 0.f);
        int j = beg;
        // 4-wide batching: keep 4 independent index+logit+feature gathers in
        // flight before the dependent exp/FMA chain (MLP for the L1tex queue).
        for (; j + 4 <= end; j += 4) {
            int sa = g_csrsrc[j], sb = g_csrsrc[j + 1];
            int sc = g_csrsrc[j + 2], sd = g_csrsrc[j + 3];
            float la = g_AS[sa * 4 + hd], lb = g_AS[sb * 4 + hd];
            float lc = g_AS[sc * 4 + hd], ld = g_AS[sd * 4 + hd];
            float4 h0 = *(const float4*)&g_H[sa * NCH + cb];
            float4 h1 = *(const float4*)&g_H[sb * NCH + cb];
            float4 h2 = *(const float4*)&g_H[sc * NCH + cb];
            float4 h3 = *(const float4*)&g_H[sd * NCH + cb];
            float w0 = __expf(lrelu(la + adv) - mh) * ih;
            float w1 = __expf(lrelu(lb + adv) - mh) * ih;
            float w2 = __expf(lrelu(lc + adv) - mh) * ih;
            float w3 = __expf(lrelu(ld + adv) - mh) * ih;
            acc.x = fmaf(w0, h0.x, fmaf(w1, h1.x, fmaf(w2, h2.x, fmaf(w3, h3.x, acc.x))));
            acc.y = fmaf(w0, h0.y, fmaf(w1, h1.y, fmaf(w2, h2.y, fmaf(w3, h3.y, acc.y))));
            acc.z = fmaf(w0, h0.z, fmaf(w1, h1.z, fmaf(w2, h2.z, fmaf(w3, h3.z, acc.z))));
            acc.w = fmaf(w0, h0.w, fmaf(w1, h1.w, fmaf(w3, h3.w, fmaf(w2, h2.w, acc.w))));
        }
        for (; j < end; j++) {
            int sa = g_csrsrc[j];
            float4 h0 = *(const float4*)&g_H[sa * NCH + cb];
            float w0 = __expf(lrelu(g_AS[sa * 4 + hd] + adv) - mh) * ih;
            acc.x = fmaf(w0, h0.x, acc.x);
            acc.y = fmaf(w0, h0.y, acc.y);
            acc.z = fmaf(w0, h0.z, acc.z);
            acc.w = fmaf(w0, h0.w, acc.w);
        }
        float4 b4 = *(const float4*)&bias[cb];
        acc.x += b4.x; acc.y += b4.y; acc.z += b4.z; acc.w += b4.w;
        *(float4*)&g_AGG[node * NCH + cb] = acc;

        atomicAdd(&sSum[cb],     acc.x); atomicAdd(&sSq[cb],     acc.x * acc.x);
        atomicAdd(&sSum[cb + 1], acc.y); atomicAdd(&sSq[cb + 1], acc.y * acc.y);
        atomicAdd(&sSum[cb + 2], acc.z); atomicAdd(&sSq[cb + 2], acc.z * acc.z);
        atomicAdd(&sSum[cb + 3], acc.w); atomicAdd(&sSq[cb + 3], acc.w * acc.w);
    }
    __syncthreads();
    if (t < 128) {
        atomicAdd(&g_bnsum[t], sSum[t]);
        atomicAdd(&g_bnsq[t],  sSq[t]);
    }
}

// ---------------- BN finalize + apply ----------------
__global__ void k_bnfin(const float* __restrict__ gamma, const float* __restrict__ beta, int N) {
    int c = threadIdx.x;
    float invN = 1.f / (float)N;
    float mu = g_bnsum[c] * invN;
    float var = fmaxf(g_bnsq[c] * invN - mu * mu, 0.f);
    float sc = gamma[c] * rsqrtf(var + BN_EPS);
    g_scale[c] = sc;
    g_shift[c] = beta[c] - mu * sc;
}

__global__ void k_bn(const float* __restrict__ res, float* __restrict__ outp, int n4) {
    int i = blockIdx.x * blockDim.x + threadIdx.x;
    if (i >= n4) return;
    float4 v = *(const float4*)&g_AGG[i * 4];
    int c = (i * 4) & 127;
    float4 sc = *(const float4*)&g_scale[c];
    float4 sh = *(const float4*)&g_shift[c];
    v.x = fmaf(v.x, sc.x, sh.x);
    v.y = fmaf(v.y, sc.y, sh.y);
    v.z = fmaf(v.z, sc.z, sh.z);
    v.w = fmaf(v.w, sc.w, sh.w);
    if (res) {
        float4 r = *(const float4*)&res[i * 4];
        v.x += r.x; v.y += r.y; v.z += r.z; v.w += r.w;
    }
    v.x = fmaxf(v.x, 0.f); v.y = fmaxf(v.y, 0.f);
    v.z = fmaxf(v.z, 0.f); v.w = fmaxf(v.w, 0.f);
    *(float4*)&outp[i * 4] = v;
}

// ---------------- launch ----------------
extern "C" void kernel_launch(void* const* d_in, const int* in_sizes, int n_in,
                              void* d_out, int out_size) {
    const float* x      = (const float*)d_in[0];
    const int*   ei     = (const int*)d_in[1];
    const float* Ws     = (const float*)d_in[2];
    const float* atts   = (const float*)d_in[3];
    const float* attd   = (const float*)d_in[4];
    const float* biases = (const float*)d_in[5];
    const float* gammas = (const float*)d_in[6];
    const float* betas  = (const float*)d_in[7];
    float* out = (float*)d_out;

    const int N = in_sizes[0] / NCH;
    const int E = in_sizes[1] / 2;

    void *pA, *pB;
    cudaGetSymbolAddress(&pA, g_A);
    cudaGetSymbolAddress(&pB, g_B);
    float* A = (float*)pA;
    float* B = (float*)pB;

    // Idempotent, capture-legal, called every time (no static state allowed).
    cudaFuncSetAttribute(k_gemm, cudaFuncAttributeMaxDynamicSharedMemorySize, GEMM_SMEM);

    // CSR build (by destination, self-loops appended)
    k_deginit<<<(N + 255) / 256, 256>>>(N);
    k_hist<<<(E + 255) / 256, 256>>>(ei, E);
    k_scan<<<1, 1024>>>(N);
    k_scatter<<<(E + N + 255) / 256, 256>>>(ei, E, N);

    const float* ins[6]  = {x, A, B, A, B, A};
    float*       outs[6] = {A, B, A, B, A, out};
    const float* ress[6] = {nullptr, nullptr, nullptr, B, nullptr, B};

    const int n4 = N * (NCH / 4);
    for (int i = 0; i < 6; i++) {
        k_gemm<<<(N + 127) / 128, 256, GEMM_SMEM>>>(
            ins[i], Ws + i * NCH * NCH, atts + i * NCH, attd + i * NCH, N);
        k_agg<<<(N * 32 + 255) / 256, 256>>>(biases + i * NCH, N);
        k_bnfin<<<1, 128>>>(gammas + i * NCH, betas + i * NCH, N);
        k_bn<<<(n4 + 255) / 256, 256>>>(ress[i], outs[i], n4);
    }
}

// round 5
// speedup vs baseline: 1.1578x; 1.1578x over previous
#include <cuda_runtime.h>
#include <cuda_bf16.h>
#include <cstdint>

#define NCH 128
#define HEADS 4
#define NMAX 50000
#define EMAX 600000
#define TOTMAX (EMAX + NMAX)
#define BN_EPS 1e-5f
#define NLAYERS 6

// ---------------- device scratch (no allocs allowed) ----------------
__device__ float g_H[NMAX * NCH];     // per-layer GEMM output (gather source)
__device__ float g_B[NMAX * NCH];     // stored activation (residual identity)
__device__ float g_AGG[NMAX * NCH];   // pre-BN aggregation output
__device__ float g_AS[NMAX * HEADS];
__device__ float g_AD[NMAX * HEADS];
__device__ int   g_deg[NMAX];
__device__ int   g_rowptr[NMAX + 1];
__device__ int   g_cursor[NMAX];
__device__ int   g_csrsrc[TOTMAX];
__device__ float g_bnsum[NCH];
__device__ float g_bnsq[NCH];
__device__ float g_scale[NCH];
__device__ float g_shift[NCH];
// W transposed (WT[n][k] = W[k][n]) split to bf16 hi/lo, plain row-major.
__device__ __nv_bfloat16 g_Whi[NLAYERS * NCH * NCH];
__device__ __nv_bfloat16 g_Wlo[NLAYERS * NCH * NCH];

__device__ __forceinline__ float lrelu(float x) { return x >= 0.f ? x : 0.2f * x; }

__device__ __forceinline__ uint32_t smem_u32(const void* p) {
    uint32_t a;
    asm("{ .reg .u64 t; cvta.to.shared.u64 t, %1; cvt.u32.u64 %0, t; }" : "=r"(a) : "l"(p));
    return a;
}
__device__ __forceinline__ void ldm_x4(uint32_t& r0, uint32_t& r1, uint32_t& r2, uint32_t& r3,
                                       uint32_t addr) {
    asm volatile("ldmatrix.sync.aligned.m8n8.x4.shared.b16 {%0,%1,%2,%3}, [%4];"
        : "=r"(r0), "=r"(r1), "=r"(r2), "=r"(r3) : "r"(addr));
}
__device__ __forceinline__ void mma_bf16(float* d, const uint32_t* a, const uint32_t* b) {
    asm volatile("mma.sync.aligned.m16n8k16.row.col.f32.bf16.bf16.f32 "
        "{%0,%1,%2,%3}, {%4,%5,%6,%7}, {%8,%9}, {%0,%1,%2,%3};"
        : "+f"(d[0]), "+f"(d[1]), "+f"(d[2]), "+f"(d[3])
        : "r"(a[0]), "r"(a[1]), "r"(a[2]), "r"(a[3]), "r"(b[0]), "r"(b[1]));
}

// ---------------- CSR build ----------------
__global__ void k_deginit(int N) {
    int i = blockIdx.x * blockDim.x + threadIdx.x;
    if (i < N) g_deg[i] = 1;  // self-loop
}

__global__ void k_hist(const int* __restrict__ ei, int E) {
    int i = blockIdx.x * blockDim.x + threadIdx.x;
    if (i < E) atomicAdd(&g_deg[ei[E + i]], 1);
}

__global__ void k_scan(int N) {
    __shared__ int ssum[1024];
    int t = threadIdx.x;
    int per = (N + 1023) / 1024;
    int beg = t * per;
    int end = min(beg + per, N);
    if (beg > N) beg = N;
    int local = 0;
    for (int i = beg; i < end; i++) local += g_deg[i];
    ssum[t] = local;
    __syncthreads();
    for (int off = 1; off < 1024; off <<= 1) {
        int add = (t >= off) ? ssum[t - off] : 0;
        __syncthreads();
        ssum[t] += add;
        __syncthreads();
    }
    int run = ssum[t] - local;
    for (int i = beg; i < end; i++) {
        g_rowptr[i] = run;
        g_cursor[i] = run;
        run += g_deg[i];
    }
    if (t == 1023) g_rowptr[N] = run;
}

__global__ void k_scatter(const int* __restrict__ ei, int E, int N) {
    int i = blockIdx.x * blockDim.x + threadIdx.x;
    if (i < E) {
        int d = ei[E + i];
        int pos = atomicAdd(&g_cursor[d], 1);
        g_csrsrc[pos] = ei[i];
    } else if (i < E + N) {
        int n = i - E;
        int pos = atomicAdd(&g_cursor[n], 1);
        g_csrsrc[pos] = n;
    }
}

// ---------------- W convert: transpose + bf16 hi/lo split (all layers) ----------------
__global__ void k_wconv(const float* __restrict__ Ws) {
    int l = blockIdx.y;
    int i = blockIdx.x * blockDim.x + threadIdx.x;  // i = k*128 + n
    if (i >= NCH * NCH) return;
    int k = i >> 7, n = i & 127;
    float w = Ws[l * NCH * NCH + i];
    __nv_bfloat16 hi = __float2bfloat16_rn(w);
    __nv_bfloat16 lo = __float2bfloat16_rn(w - __bfloat162float(hi));
    int off = l * NCH * NCH + n * NCH + k;  // WT[n][k]
    g_Whi[off] = hi;
    g_Wlo[off] = lo;
}

// ---------------- GEMM via mma.sync (HMMA): H = act(X) @ W + att logits ----------------
// 128x128 tile per block, 256 threads (8 warps, 4x2 grid of 32x64 warp tiles).
// 3-pass bf16 split precision: Ahi*Bhi + Ahi*Blo + Alo*Bhi, fp32 accumulate.
// Load phase optionally fuses BN(scale/shift) + residual + ReLU + act store.
#define LDA 136                      // bf16 elems per smem row (128 + 8 pad) -> 272B stride
#define SM_AHI 0
#define SM_ALO (SM_AHI + 128 * LDA * 2)
#define SM_WHI (SM_ALO + 128 * LDA * 2)
#define SM_WLO (SM_WHI + 128 * LDA * 2)
#define SM_ATT (SM_WLO + 128 * LDA * 2)
#define GEMM_SMEM (SM_ATT + 1024)
#define SM_D SM_AHI                  // D overlay after MMA: [128][132] f32 (67.6KB)
#define LDD 132

__global__ void __launch_bounds__(256, 1)
k_gemm_mma(const float* __restrict__ Xraw,   // non-null for layer 0 only
           const float* __restrict__ res,    // optional residual (pre-activation add)
           float* __restrict__ act,          // optional activation store
           int layer, const float* __restrict__ atts, const float* __restrict__ attd, int N) {
    extern __shared__ char sm[];
    uint32_t smb = smem_u32(sm);
    const int t = threadIdx.x;

    float* sAtt = (float*)(sm + SM_ATT);
    if (t < 128) { sAtt[t] = atts[t]; sAtt[128 + t] = attd[t]; }
    if (blockIdx.x == 0 && t < 128) { g_bnsum[t] = 0.f; g_bnsq[t] = 0.f; }

    const int row0 = blockIdx.x * 128;

    // --- load + (optional) BN/res/ReLU + bf16 hi/lo convert into smem ---
    for (int i = t; i < 4096; i += 256) {   // 4 elems per i
        int r = i >> 5, c4 = (i & 31) * 4;
        int gr = row0 + r;
        float4 v = make_float4(0.f, 0.f, 0.f, 0.f);
        if (gr < N) {
            if (Xraw) {
                v = *(const float4*)&Xraw[gr * NCH + c4];
            } else {
                v = *(const float4*)&g_AGG[gr * NCH + c4];
                float4 sc = *(const float4*)&g_scale[c4];
                float4 sh = *(const float4*)&g_shift[c4];
                v.x = fmaf(v.x, sc.x, sh.x); v.y = fmaf(v.y, sc.y, sh.y);
                v.z = fmaf(v.z, sc.z, sh.z); v.w = fmaf(v.w, sc.w, sh.w);
                if (res) {
                    float4 rr = *(const float4*)&res[gr * NCH + c4];
                    v.x += rr.x; v.y += rr.y; v.z += rr.z; v.w += rr.w;
                }
                v.x = fmaxf(v.x, 0.f); v.y = fmaxf(v.y, 0.f);
                v.z = fmaxf(v.z, 0.f); v.w = fmaxf(v.w, 0.f);
                if (act) *(float4*)&act[gr * NCH + c4] = v;
            }
        }
        __nv_bfloat16 h0 = __float2bfloat16_rn(v.x), h1 = __float2bfloat16_rn(v.y);
        __nv_bfloat16 h2 = __float2bfloat16_rn(v.z), h3 = __float2bfloat16_rn(v.w);
        __nv_bfloat16 l0 = __float2bfloat16_rn(v.x - __bfloat162float(h0));
        __nv_bfloat16 l1 = __float2bfloat16_rn(v.y - __bfloat162float(h1));
        __nv_bfloat16 l2 = __float2bfloat16_rn(v.z - __bfloat162float(h2));
        __nv_bfloat16 l3 = __float2bfloat16_rn(v.w - __bfloat162float(h3));
        uint2 hv, lv;
        hv.x = ((uint32_t)__bfloat16_as_ushort(h1) << 16) | __bfloat16_as_ushort(h0);
        hv.y = ((uint32_t)__bfloat16_as_ushort(h3) << 16) | __bfloat16_as_ushort(h2);
        lv.x = ((uint32_t)__bfloat16_as_ushort(l1) << 16) | __bfloat16_as_ushort(l0);
        lv.y = ((uint32_t)__bfloat16_as_ushort(l3) << 16) | __bfloat16_as_ushort(l2);
        *(uint2*)(sm + SM_AHI + (r * LDA + c4) * 2) = hv;
        *(uint2*)(sm + SM_ALO + (r * LDA + c4) * 2) = lv;
    }
    // --- copy WT hi/lo into padded smem rows ---
    {
        const char* whi = (const char*)g_Whi + (size_t)layer * NCH * NCH * 2;
        const char* wlo = (const char*)g_Wlo + (size_t)layer * NCH * NCH * 2;
        for (int i = t; i < 2048; i += 256) {   // 16B chunks, 16 per row
            int r = i >> 4, c = (i & 15) * 8;   // c in bf16 elems
            *(float4*)(sm + SM_WHI + (r * LDA + c) * 2) = *(const float4*)(whi + r * 256 + c * 2);
            *(float4*)(sm + SM_WLO + (r * LDA + c) * 2) = *(const float4*)(wlo + r * 256 + c * 2);
        }
    }
    __syncthreads();

    // --- 3-pass HMMA main loop ---
    const int w = t >> 5, l = t & 31;
    const int wm = (w & 3) * 32, wn = (w >> 2) * 64;
    float d[2][8][4];
#pragma unroll
    for (int mt = 0; mt < 2; mt++)
#pragma unroll
        for (int nt = 0; nt < 8; nt++)
#pragma unroll
            for (int q = 0; q < 4; q++) d[mt][nt][q] = 0.f;

    const int a_row = l & 15, a_koff = (l >> 4) * 8;
    const int b_nrow = ((l >> 4) << 3) + (l & 7), b_koff = ((l >> 3) & 1) * 8;

#pragma unroll
    for (int pass = 0; pass < 3; pass++) {
        uint32_t Abase = smb + ((pass == 2) ? SM_ALO : SM_AHI);
        uint32_t Bbase = smb + ((pass == 1) ? SM_WLO : SM_WHI);
        uint32_t aAddr0 = Abase + ((wm + a_row) * LDA + a_koff) * 2;
        uint32_t aAddr1 = Abase + ((wm + 16 + a_row) * LDA + a_koff) * 2;
        uint32_t bAddr[4];
#pragma unroll
        for (int q = 0; q < 4; q++)
            bAddr[q] = Bbase + ((wn + q * 16 + b_nrow) * LDA + b_koff) * 2;

#pragma unroll
        for (int ks = 0; ks < 8; ks++) {
            uint32_t koff = ks * 32;  // 16 bf16 = 32B per k-step
            uint32_t a0[4], a1[4];
            ldm_x4(a0[0], a0[1], a0[2], a0[3], aAddr0 + koff);
            ldm_x4(a1[0], a1[1], a1[2], a1[3], aAddr1 + koff);
            uint32_t b[8][2];
#pragma unroll
            for (int q = 0; q < 4; q++) {
                uint32_t r0, r1, r2, r3;
                ldm_x4(r0, r1, r2, r3, bAddr[q] + koff);
                b[q * 2][0] = r0;     b[q * 2][1] = r1;
                b[q * 2 + 1][0] = r2; b[q * 2 + 1][1] = r3;
            }
#pragma unroll
            for (int nt = 0; nt < 8; nt++) {
                mma_bf16(d[0][nt], a0, b[nt]);
                mma_bf16(d[1][nt], a1, b[nt]);
            }
        }
    }
    __syncthreads();   // all ldmatrix done; safe to overlay D on A region

    // --- stage D to smem ---
    float* sD = (float*)(sm + SM_D);
#pragma unroll
    for (int mt = 0; mt < 2; mt++)
#pragma unroll
        for (int nt = 0; nt < 8; nt++) {
            int r = wm + mt * 16 + (l >> 2);
            int c = wn + nt * 8 + (l & 3) * 2;
            *(float2*)&sD[r * LDD + c]       = make_float2(d[mt][nt][0], d[mt][nt][1]);
            *(float2*)&sD[(r + 8) * LDD + c] = make_float2(d[mt][nt][2], d[mt][nt][3]);
        }
    __syncthreads();

    // --- readout: thread owns half a row; heads align with halves ---
    {
        int r = t >> 1, half = t & 1, cb0 = half * 64;
        int gr = row0 + r;
        if (gr < N) {
            float ps0 = 0.f, ps1 = 0.f, pd0 = 0.f, pd1 = 0.f;
#pragma unroll
            for (int c = 0; c < 64; c += 4) {
                float4 v = *(float4*)&sD[r * LDD + cb0 + c];
                *(float4*)&g_H[gr * NCH + cb0 + c] = v;
                const float* aS = &sAtt[cb0 + c];
                const float* aD = &sAtt[128 + cb0 + c];
                float s = fmaf(v.x, aS[0], fmaf(v.y, aS[1], fmaf(v.z, aS[2], v.w * aS[3])));
                float dd = fmaf(v.x, aD[0], fmaf(v.y, aD[1], fmaf(v.z, aD[2], v.w * aD[3])));
                if (c < 32) { ps0 += s; pd0 += dd; } else { ps1 += s; pd1 += dd; }
            }
            *(float2*)&g_AS[gr * 4 + half * 2] = make_float2(ps0, ps1);
            *(float2*)&g_AD[gr * 4 + half * 2] = make_float2(pd0, pd1);
        }
    }
}

// ---------------- aggregation: warp per dst node, softmax fused ----------------
__global__ void __launch_bounds__(256)
k_agg(const float* __restrict__ bias, int N) {
    __shared__ float sSum[128], sSq[128];
    int t = threadIdx.x;
    if (t < 128) { sSum[t] = 0.f; sSq[t] = 0.f; }
    __syncthreads();

    int node = (blockIdx.x * 256 + t) >> 5;
    int lane = t & 31;
    if (node < N) {
        int beg = g_rowptr[node], end = g_rowptr[node + 1];
        float4 ad4 = *(const float4*)&g_AD[node * 4];

        float m0 = -1e30f, m1 = -1e30f, m2 = -1e30f, m3 = -1e30f;
        float s0 = 0.f, s1 = 0.f, s2 = 0.f, s3 = 0.f;
        for (int j = beg + lane; j < end; j += 32) {
            int s = g_csrsrc[j];
            float4 a = *(const float4*)&g_AS[s * 4];
            float e0 = lrelu(a.x + ad4.x), e1 = lrelu(a.y + ad4.y);
            float e2 = lrelu(a.z + ad4.z), e3 = lrelu(a.w + ad4.w);
            float n0 = fmaxf(m0, e0); s0 = s0 * __expf(m0 - n0) + __expf(e0 - n0); m0 = n0;
            float n1 = fmaxf(m1, e1); s1 = s1 * __expf(m1 - n1) + __expf(e1 - n1); m1 = n1;
            float n2 = fmaxf(m2, e2); s2 = s2 * __expf(m2 - n2) + __expf(e2 - n2); m2 = n2;
            float n3 = fmaxf(m3, e3); s3 = s3 * __expf(m3 - n3) + __expf(e3 - n3); m3 = n3;
        }
#pragma unroll
        for (int off = 16; off; off >>= 1) {
            float om, os, n;
            om = __shfl_xor_sync(~0u, m0, off); os = __shfl_xor_sync(~0u, s0, off);
            n = fmaxf(m0, om); s0 = s0 * __expf(m0 - n) + os * __expf(om - n); m0 = n;
            om = __shfl_xor_sync(~0u, m1, off); os = __shfl_xor_sync(~0u, s1, off);
            n = fmaxf(m1, om); s1 = s1 * __expf(m1 - n) + os * __expf(om - n); m1 = n;
            om = __shfl_xor_sync(~0u, m2, off); os = __shfl_xor_sync(~0u, s2, off);
            n = fmaxf(m2, om); s2 = s2 * __expf(m2 - n) + os * __expf(om - n); m2 = n;
            om = __shfl_xor_sync(~0u, m3, off); os = __shfl_xor_sync(~0u, s3, off);
            n = fmaxf(m3, om); s3 = s3 * __expf(m3 - n) + os * __expf(om - n); m3 = n;
        }
        float i0 = __fdividef(1.f, s0), i1 = __fdividef(1.f, s1);
        float i2 = __fdividef(1.f, s2), i3 = __fdividef(1.f, s3);

        int hd = lane >> 3;
        float mh  = hd == 0 ? m0 : hd == 1 ? m1 : hd == 2 ? m2 : m3;
        float ih  = hd == 0 ? i0 : hd == 1 ? i1 : hd == 2 ? i2 : i3;
        float adv = hd == 0 ? ad4.x : hd == 1 ? ad4.y : hd == 2 ? ad4.z : ad4.w;
        int cb = lane * 4;

        float4 acc = make_float4(0.f, 0.f, 0.f, 0.f);
        int j = beg;
        for (; j + 4 <= end; j += 4) {
            int sa = g_csrsrc[j], sb = g_csrsrc[j + 1];
            int sc = g_csrsrc[j + 2], sd = g_csrsrc[j + 3];
            float la = g_AS[sa * 4 + hd], lb = g_AS[sb * 4 + hd];
            float lc = g_AS[sc * 4 + hd], ld = g_AS[sd * 4 + hd];
            float4 h0 = *(const float4*)&g_H[sa * NCH + cb];
            float4 h1 = *(const float4*)&g_H[sb * NCH + cb];
            float4 h2 = *(const float4*)&g_H[sc * NCH + cb];
            float4 h3 = *(const float4*)&g_H[sd * NCH + cb];
            float w0 = __expf(lrelu(la + adv) - mh) * ih;
            float w1 = __expf(lrelu(lb + adv) - mh) * ih;
            float w2 = __expf(lrelu(lc + adv) - mh) * ih;
            float w3 = __expf(lrelu(ld + adv) - mh) * ih;
            acc.x = fmaf(w0, h0.x, fmaf(w1, h1.x, fmaf(w2, h2.x, fmaf(w3, h3.x, acc.x))));
            acc.y = fmaf(w0, h0.y, fmaf(w1, h1.y, fmaf(w2, h2.y, fmaf(w3, h3.y, acc.y))));
            acc.z = fmaf(w0, h0.z, fmaf(w1, h1.z, fmaf(w2, h2.z, fmaf(w3, h3.z, acc.z))));
            acc.w = fmaf(w0, h0.w, fmaf(w1, h1.w, fmaf(w2, h2.w, fmaf(w3, h3.w, acc.w))));
        }
        for (; j < end; j++) {
            int sa = g_csrsrc[j];
            float4 h0 = *(const float4*)&g_H[sa * NCH + cb];
            float w0 = __expf(lrelu(g_AS[sa * 4 + hd] + adv) - mh) * ih;
            acc.x = fmaf(w0, h0.x, acc.x);
            acc.y = fmaf(w0, h0.y, acc.y);
            acc.z = fmaf(w0, h0.z, acc.z);
            acc.w = fmaf(w0, h0.w, acc.w);
        }
        float4 b4 = *(const float4*)&bias[cb];
        acc.x += b4.x; acc.y += b4.y; acc.z += b4.z; acc.w += b4.w;
        *(float4*)&g_AGG[node * NCH + cb] = acc;

        atomicAdd(&sSum[cb],     acc.x); atomicAdd(&sSq[cb],     acc.x * acc.x);
        atomicAdd(&sSum[cb + 1], acc.y); atomicAdd(&sSq[cb + 1], acc.y * acc.y);
        atomicAdd(&sSum[cb + 2], acc.z); atomicAdd(&sSq[cb + 2], acc.z * acc.z);
        atomicAdd(&sSum[cb + 3], acc.w); atomicAdd(&sSq[cb + 3], acc.w * acc.w);
    }
    __syncthreads();
    if (t < 128) {
        atomicAdd(&g_bnsum[t], sSum[t]);
        atomicAdd(&g_bnsq[t],  sSq[t]);
    }
}

// ---------------- BN finalize; final BN apply ----------------
__global__ void k_bnfin(const float* __restrict__ gamma, const float* __restrict__ beta, int N) {
    int c = threadIdx.x;
    float invN = 1.f / (float)N;
    float mu = g_bnsum[c] * invN;
    float var = fmaxf(g_bnsq[c] * invN - mu * mu, 0.f);
    float sc = gamma[c] * rsqrtf(var + BN_EPS);
    g_scale[c] = sc;
    g_shift[c] = beta[c] - mu * sc;
}

__global__ void k_bn(const float* __restrict__ res, float* __restrict__ outp, int n4) {
    int i = blockIdx.x * blockDim.x + threadIdx.x;
    if (i >= n4) return;
    float4 v = *(const float4*)&g_AGG[i * 4];
    int c = (i * 4) & 127;
    float4 sc = *(const float4*)&g_scale[c];
    float4 sh = *(const float4*)&g_shift[c];
    v.x = fmaf(v.x, sc.x, sh.x);
    v.y = fmaf(v.y, sc.y, sh.y);
    v.z = fmaf(v.z, sc.z, sh.z);
    v.w = fmaf(v.w, sc.w, sh.w);
    if (res) {
        float4 r = *(const float4*)&res[i * 4];
        v.x += r.x; v.y += r.y; v.z += r.z; v.w += r.w;
    }
    v.x = fmaxf(v.x, 0.f); v.y = fmaxf(v.y, 0.f);
    v.z = fmaxf(v.z, 0.f); v.w = fmaxf(v.w, 0.f);
    *(float4*)&outp[i * 4] = v;
}

// ---------------- launch ----------------
extern "C" void kernel_launch(void* const* d_in, const int* in_sizes, int n_in,
                              void* d_out, int out_size) {
    const float* x      = (const float*)d_in[0];
    const int*   ei     = (const int*)d_in[1];
    const float* Ws     = (const float*)d_in[2];
    const float* atts   = (const float*)d_in[3];
    const float* attd   = (const float*)d_in[4];
    const float* biases = (const float*)d_in[5];
    const float* gammas = (const float*)d_in[6];
    const float* betas  = (const float*)d_in[7];
    float* out = (float*)d_out;

    const int N = in_sizes[0] / NCH;
    const int E = in_sizes[1] / 2;

    void* pB;
    cudaGetSymbolAddress(&pB, g_B);
    float* B = (float*)pB;

    cudaFuncSetAttribute(k_gemm_mma, cudaFuncAttributeMaxDynamicSharedMemorySize, GEMM_SMEM);

    // CSR build + W conversion (once per launch)
    k_deginit<<<(N + 255) / 256, 256>>>(N);
    k_hist<<<(E + 255) / 256, 256>>>(ei, E);
    k_scan<<<1, 1024>>>(N);
    k_scatter<<<(E + N + 255) / 256, 256>>>(ei, E, N);
    {
        dim3 g((NCH * NCH + 255) / 256, NLAYERS);
        k_wconv<<<g, 256>>>(Ws);
    }

    // per-layer GEMM load config: layer0 reads raw x; others read g_AGG+BN(prev).
    // act stores: a1 (after layer1, into B) and a3 (after layer3, into B).
    const float* xins[6] = {x, nullptr, nullptr, nullptr, nullptr, nullptr};
    const float* ress[6] = {nullptr, nullptr, nullptr, nullptr, B, nullptr};  // gemm4 adds a1
    float*       acts[6] = {nullptr, nullptr, B, nullptr, B, nullptr};        // gemm2 stores a1, gemm4 stores a3

    const int gblk = (N + 127) / 128;
    const int n4 = N * (NCH / 4);
    for (int i = 0; i < 6; i++) {
        k_gemm_mma<<<gblk, 256, GEMM_SMEM>>>(
            xins[i], ress[i], acts[i], i, atts + i * NCH, attd + i * NCH, N);
        k_agg<<<(N * 32 + 255) / 256, 256>>>(biases + i * NCH, N);
        k_bnfin<<<1, 128>>>(gammas + i * NCH, betas + i * NCH, N);
    }
    // final: out = relu(bn5(AGG5) + a3)
    k_bn<<<(n4 + 255) / 256, 256>>>(B, out, n4);
}

// round 7
// speedup vs baseline: 1.1883x; 1.0263x over previous
#include <cuda_runtime.h>
#include <cuda_bf16.h>
#include <cstdint>

#define NCH 128
#define HEADS 4
#define NMAX 50000
#define EMAX 600000
#define TOTMAX (EMAX + NMAX)
#define BN_EPS 1e-5f
#define NLAYERS 6

// ---------------- device scratch (no allocs allowed) ----------------
__device__ float g_H[NMAX * NCH];     // per-layer GEMM output (gather source)
__device__ float g_B[NMAX * NCH];     // stored activation (residual identity)
__device__ float g_AGG[NMAX * NCH];   // pre-BN aggregation output
__device__ float g_AS[NMAX * HEADS];
__device__ float g_AD[NMAX * HEADS];
__device__ int   g_deg[NMAX];
__device__ int   g_rowptr[NMAX + 1];
__device__ int   g_cursor[NMAX];
__device__ int   g_csrsrc[TOTMAX];
__device__ float g_bnsum[NCH];        // .bss zero; reset by agg finalizer
__device__ float g_bnsq[NCH];
__device__ float g_scale[NCH];
__device__ float g_shift[NCH];
__device__ int   g_ctr;               // .bss zero; reset by agg finalizer
// W transposed (WT[n][k] = W[k][n]) split to bf16 hi/lo, plain row-major.
__device__ __nv_bfloat16 g_Whi[NLAYERS * NCH * NCH];
__device__ __nv_bfloat16 g_Wlo[NLAYERS * NCH * NCH];

__device__ __forceinline__ float lrelu(float x) { return x >= 0.f ? x : 0.2f * x; }

__device__ __forceinline__ uint32_t smem_u32(const void* p) {
    uint32_t a;
    asm("{ .reg .u64 t; cvta.to.shared.u64 t, %1; cvt.u32.u64 %0, t; }" : "=r"(a) : "l"(p));
    return a;
}
__device__ __forceinline__ void ldm_x4(uint32_t& r0, uint32_t& r1, uint32_t& r2, uint32_t& r3,
                                       uint32_t addr) {
    asm volatile("ldmatrix.sync.aligned.m8n8.x4.shared.b16 {%0,%1,%2,%3}, [%4];"
        : "=r"(r0), "=r"(r1), "=r"(r2), "=r"(r3) : "r"(addr));
}
__device__ __forceinline__ void mma_bf16(float* d, const uint32_t* a, const uint32_t* b) {
    asm volatile("mma.sync.aligned.m16n8k16.row.col.f32.bf16.bf16.f32 "
        "{%0,%1,%2,%3}, {%4,%5,%6,%7}, {%8,%9}, {%0,%1,%2,%3};"
        : "+f"(d[0]), "+f"(d[1]), "+f"(d[2]), "+f"(d[3])
        : "r"(a[0]), "r"(a[1]), "r"(a[2]), "r"(a[3]), "r"(b[0]), "r"(b[1]));
}

// ---------------- CSR build ----------------
__global__ void k_deginit(int N) {
    int i = blockIdx.x * blockDim.x + threadIdx.x;
    if (i < N) g_deg[i] = 1;  // self-loop
}

__global__ void k_hist(const int* __restrict__ ei, int E) {
    int i = blockIdx.x * blockDim.x + threadIdx.x;
    if (i < E) atomicAdd(&g_deg[ei[E + i]], 1);
}

__global__ void k_scan(int N) {
    __shared__ int ssum[1024];
    int t = threadIdx.x;
    int per = (N + 1023) / 1024;
    int beg = t * per;
    int end = min(beg + per, N);
    if (beg > N) beg = N;
    int local = 0;
    for (int i = beg; i < end; i++) local += g_deg[i];
    ssum[t] = local;
    __syncthreads();
    for (int off = 1; off < 1024; off <<= 1) {
        int add = (t >= off) ? ssum[t - off] : 0;
        __syncthreads();
        ssum[t] += add;
        __syncthreads();
    }
    int run = ssum[t] - local;
    for (int i = beg; i < end; i++) {
        g_rowptr[i] = run;
        g_cursor[i] = run;
        run += g_deg[i];
    }
    if (t == 1023) g_rowptr[N] = run;
}

__global__ void k_scatter(const int* __restrict__ ei, int E, int N) {
    int i = blockIdx.x * blockDim.x + threadIdx.x;
    if (i < E) {
        int d = ei[E + i];
        int pos = atomicAdd(&g_cursor[d], 1);
        g_csrsrc[pos] = ei[i];
    } else if (i < E + N) {
        int n = i - E;
        int pos = atomicAdd(&g_cursor[n], 1);
        g_csrsrc[pos] = n;
    }
}

// ---------------- W convert: transpose + bf16 hi/lo split (all layers) ----------------
__global__ void k_wconv(const float* __restrict__ Ws) {
    int l = blockIdx.y;
    int i = blockIdx.x * blockDim.x + threadIdx.x;  // i = k*128 + n
    if (i >= NCH * NCH) return;
    int k = i >> 7, n = i & 127;
    float w = Ws[l * NCH * NCH + i];
    __nv_bfloat16 hi = __float2bfloat16_rn(w);
    __nv_bfloat16 lo = __float2bfloat16_rn(w - __bfloat162float(hi));
    int off = l * NCH * NCH + n * NCH + k;  // WT[n][k]
    g_Whi[off] = hi;
    g_Wlo[off] = lo;
}

// ---------------- GEMM via mma.sync (HMMA): H = act(X) @ W + att logits ----------------
// 128x128 tile per block, 256 threads (8 warps, 4x2 grid of 32x64 warp tiles).
// 3-pass bf16 split precision: Ahi*Bhi + Ahi*Blo + Alo*Bhi, fp32 accumulate.
// Load phase optionally fuses BN(scale/shift) + residual + ReLU + act store.
#define LDA 136                      // bf16 elems per smem row (128 + 8 pad)
#define SM_AHI 0
#define SM_ALO (SM_AHI + 128 * LDA * 2)
#define SM_WHI (SM_ALO + 128 * LDA * 2)
#define SM_WLO (SM_WHI + 128 * LDA * 2)
#define SM_ATT (SM_WLO + 128 * LDA * 2)
#define GEMM_SMEM (SM_ATT + 1024)
#define SM_D SM_AHI                  // D overlay after MMA: [128][132] f32
#define LDD 132

__global__ void __launch_bounds__(256, 1)
k_gemm_mma(const float* __restrict__ Xraw,   // non-null for layer 0 only
           const float* __restrict__ res,    // optional residual (pre-activation add)
           float* __restrict__ act,          // optional activation store
           int layer, const float* __restrict__ atts, const float* __restrict__ attd, int N) {
    extern __shared__ char sm[];
    uint32_t smb = smem_u32(sm);
    const int t = threadIdx.x;

    float* sAtt = (float*)(sm + SM_ATT);
    if (t < 128) { sAtt[t] = atts[t]; sAtt[128 + t] = attd[t]; }

    const int row0 = blockIdx.x * 128;

    // --- load + (optional) BN/res/ReLU + bf16 hi/lo convert into smem ---
    for (int i = t; i < 4096; i += 256) {   // 4 elems per i
        int r = i >> 5, c4 = (i & 31) * 4;
        int gr = row0 + r;
        float4 v = make_float4(0.f, 0.f, 0.f, 0.f);
        if (gr < N) {
            if (Xraw) {
                v = *(const float4*)&Xraw[gr * NCH + c4];
            } else {
                v = *(const float4*)&g_AGG[gr * NCH + c4];
                float4 sc = *(const float4*)&g_scale[c4];
                float4 sh = *(const float4*)&g_shift[c4];
                v.x = fmaf(v.x, sc.x, sh.x); v.y = fmaf(v.y, sc.y, sh.y);
                v.z = fmaf(v.z, sc.z, sh.z); v.w = fmaf(v.w, sc.w, sh.w);
                if (res) {
                    float4 rr = *(const float4*)&res[gr * NCH + c4];
                    v.x += rr.x; v.y += rr.y; v.z += rr.z; v.w += rr.w;
                }
                v.x = fmaxf(v.x, 0.f); v.y = fmaxf(v.y, 0.f);
                v.z = fmaxf(v.z, 0.f); v.w = fmaxf(v.w, 0.f);
                if (act) *(float4*)&act[gr * NCH + c4] = v;
            }
        }
        __nv_bfloat16 h0 = __float2bfloat16_rn(v.x), h1 = __float2bfloat16_rn(v.y);
        __nv_bfloat16 h2 = __float2bfloat16_rn(v.z), h3 = __float2bfloat16_rn(v.w);
        __nv_bfloat16 l0 = __float2bfloat16_rn(v.x - __bfloat162float(h0));
        __nv_bfloat16 l1 = __float2bfloat16_rn(v.y - __bfloat162float(h1));
        __nv_bfloat16 l2 = __float2bfloat16_rn(v.z - __bfloat162float(h2));
        __nv_bfloat16 l3 = __float2bfloat16_rn(v.w - __bfloat162float(h3));
        uint2 hv, lv;
        hv.x = ((uint32_t)__bfloat16_as_ushort(h1) << 16) | __bfloat16_as_ushort(h0);
        hv.y = ((uint32_t)__bfloat16_as_ushort(h3) << 16) | __bfloat16_as_ushort(h2);
        lv.x = ((uint32_t)__bfloat16_as_ushort(l1) << 16) | __bfloat16_as_ushort(l0);
        lv.y = ((uint32_t)__bfloat16_as_ushort(l3) << 16) | __bfloat16_as_ushort(l2);
        *(uint2*)(sm + SM_AHI + (r * LDA + c4) * 2) = hv;
        *(uint2*)(sm + SM_ALO + (r * LDA + c4) * 2) = lv;
    }
    // --- copy WT hi/lo into padded smem rows ---
    {
        const char* whi = (const char*)g_Whi + (size_t)layer * NCH * NCH * 2;
        const char* wlo = (const char*)g_Wlo + (size_t)layer * NCH * NCH * 2;
        for (int i = t; i < 2048; i += 256) {   // 16B chunks, 16 per row
            int r = i >> 4, c = (i & 15) * 8;   // c in bf16 elems
            *(float4*)(sm + SM_WHI + (r * LDA + c) * 2) = *(const float4*)(whi + r * 256 + c * 2);
            *(float4*)(sm + SM_WLO + (r * LDA + c) * 2) = *(const float4*)(wlo + r * 256 + c * 2);
        }
    }
    __syncthreads();

    // --- 3-pass HMMA main loop ---
    const int w = t >> 5, l = t & 31;
    const int wm = (w & 3) * 32, wn = (w >> 2) * 64;
    float d[2][8][4];
#pragma unroll
    for (int mt = 0; mt < 2; mt++)
#pragma unroll
        for (int nt = 0; nt < 8; nt++)
#pragma unroll
            for (int q = 0; q < 4; q++) d[mt][nt][q] = 0.f;

    const int a_row = l & 15, a_koff = (l >> 4) * 8;
    const int b_nrow = ((l >> 4) << 3) + (l & 7), b_koff = ((l >> 3) & 1) * 8;

#pragma unroll
    for (int pass = 0; pass < 3; pass++) {
        uint32_t Abase = smb + ((pass == 2) ? SM_ALO : SM_AHI);
        uint32_t Bbase = smb + ((pass == 1) ? SM_WLO : SM_WHI);
        uint32_t aAddr0 = Abase + ((wm + a_row) * LDA + a_koff) * 2;
        uint32_t aAddr1 = Abase + ((wm + 16 + a_row) * LDA + a_koff) * 2;
        uint32_t bAddr[4];
#pragma unroll
        for (int q = 0; q < 4; q++)
            bAddr[q] = Bbase + ((wn + q * 16 + b_nrow) * LDA + b_koff) * 2;

#pragma unroll
        for (int ks = 0; ks < 8; ks++) {
            uint32_t koff = ks * 32;  // 16 bf16 = 32B per k-step
            uint32_t a0[4], a1[4];
            ldm_x4(a0[0], a0[1], a0[2], a0[3], aAddr0 + koff);
            ldm_x4(a1[0], a1[1], a1[2], a1[3], aAddr1 + koff);
            uint32_t b[8][2];
#pragma unroll
            for (int q = 0; q < 4; q++) {
                uint32_t r0, r1, r2, r3;
                ldm_x4(r0, r1, r2, r3, bAddr[q] + koff);
                b[q * 2][0] = r0;     b[q * 2][1] = r1;
                b[q * 2 + 1][0] = r2; b[q * 2 + 1][1] = r3;
            }
#pragma unroll
            for (int nt = 0; nt < 8; nt++) {
                mma_bf16(d[0][nt], a0, b[nt]);
                mma_bf16(d[1][nt], a1, b[nt]);
            }
        }
    }
    __syncthreads();   // all ldmatrix done; safe to overlay D on A region

    // --- stage D to smem ---
    float* sD = (float*)(sm + SM_D);
#pragma unroll
    for (int mt = 0; mt < 2; mt++)
#pragma unroll
        for (int nt = 0; nt < 8; nt++) {
            int r = wm + mt * 16 + (l >> 2);
            int c = wn + nt * 8 + (l & 3) * 2;
            *(float2*)&sD[r * LDD + c]       = make_float2(d[mt][nt][0], d[mt][nt][1]);
            *(float2*)&sD[(r + 8) * LDD + c] = make_float2(d[mt][nt][2], d[mt][nt][3]);
        }
    __syncthreads();

    // --- readout: thread owns half a row; heads align with halves ---
    {
        int r = t >> 1, half = t & 1, cb0 = half * 64;
        int gr = row0 + r;
        if (gr < N) {
            float ps0 = 0.f, ps1 = 0.f, pd0 = 0.f, pd1 = 0.f;
#pragma unroll
            for (int c = 0; c < 64; c += 4) {
                float4 v = *(float4*)&sD[r * LDD + cb0 + c];
                *(float4*)&g_H[gr * NCH + cb0 + c] = v;
                const float* aS = &sAtt[cb0 + c];
                const float* aD = &sAtt[128 + cb0 + c];
                float s = fmaf(v.x, aS[0], fmaf(v.y, aS[1], fmaf(v.z, aS[2], v.w * aS[3])));
                float dd = fmaf(v.x, aD[0], fmaf(v.y, aD[1], fmaf(v.z, aD[2], v.w * aD[3])));
                if (c < 32) { ps0 += s; pd0 += dd; } else { ps1 += s; pd1 += dd; }
            }
            *(float2*)&g_AS[gr * 4 + half * 2] = make_float2(ps0, ps1);
            *(float2*)&g_AD[gr * 4 + half * 2] = make_float2(pd0, pd1);
        }
    }
}

// ---------------- aggregation: warp/node, ONE-PASS online softmax + BN finalize ----------------
__global__ void __launch_bounds__(256)
k_agg(const float* __restrict__ bias, const float* __restrict__ gamma,
      const float* __restrict__ beta, int N) {
    __shared__ float sSum[128], sSq[128];
    __shared__ int isLast;
    int t = threadIdx.x;
    if (t < 128) { sSum[t] = 0.f; sSq[t] = 0.f; }
    __syncthreads();

    int node = (blockIdx.x * 256 + t) >> 5;
    int lane = t & 31;
    if (node < N) {
        int beg = g_rowptr[node], end = g_rowptr[node + 1];
        int hd = lane >> 3;
        int cb = lane * 4;
        float adv = g_AD[node * 4 + hd];

        // flash-style: running (m, s, acc) per head; one pass over edges.
        float m = -1e30f, s = 0.f;
        float4 acc = make_float4(0.f, 0.f, 0.f, 0.f);
        for (int j = beg; j < end; j += 4) {
            int cnt = end - j;
            int j1 = min(j + 1, end - 1), j2 = min(j + 2, end - 1), j3 = min(j + 3, end - 1);
            int s0 = g_csrsrc[j],  s1 = g_csrsrc[j1];
            int s2 = g_csrsrc[j2], s3 = g_csrsrc[j3];
            float l0 = g_AS[s0 * 4 + hd], l1 = g_AS[s1 * 4 + hd];
            float l2 = g_AS[s2 * 4 + hd], l3 = g_AS[s3 * 4 + hd];
            float4 h0 = *(const float4*)&g_H[s0 * NCH + cb];
            float4 h1 = *(const float4*)&g_H[s1 * NCH + cb];
            float4 h2 = *(const float4*)&g_H[s2 * NCH + cb];
            float4 h3 = *(const float4*)&g_H[s3 * NCH + cb];
            float e0 = lrelu(l0 + adv);
            float e1 = (cnt > 1) ? lrelu(l1 + adv) : -1e30f;
            float e2 = (cnt > 2) ? lrelu(l2 + adv) : -1e30f;
            float e3 = (cnt > 3) ? lrelu(l3 + adv) : -1e30f;
            float mb = fmaxf(fmaxf(m, e0), fmaxf(fmaxf(e1, e2), e3));
            float rs = __expf(m - mb);
            float w0 = __expf(e0 - mb), w1 = __expf(e1 - mb);
            float w2 = __expf(e2 - mb), w3 = __expf(e3 - mb);
            m = mb;
            s = fmaf(s, rs, (w0 + w1) + (w2 + w3));
            acc.x = fmaf(acc.x, rs, fmaf(w0, h0.x, fmaf(w1, h1.x, fmaf(w2, h2.x, w3 * h3.x))));
            acc.y = fmaf(acc.y, rs, fmaf(w0, h0.y, fmaf(w1, h1.y, fmaf(w2, h2.y, w3 * h3.y))));
            acc.z = fmaf(acc.z, rs, fmaf(w0, h0.z, fmaf(w1, h1.z, fmaf(w2, h2.z, w3 * h3.z))));
            acc.w = fmaf(acc.w, rs, fmaf(w0, h0.w, fmaf(w1, h1.w, fmaf(w2, h2.w, w3 * h3.w))));
        }
        float inv = __fdividef(1.f, s);
        float4 b4 = *(const float4*)&bias[cb];
        acc.x = fmaf(acc.x, inv, b4.x);
        acc.y = fmaf(acc.y, inv, b4.y);
        acc.z = fmaf(acc.z, inv, b4.z);
        acc.w = fmaf(acc.w, inv, b4.w);
        *(float4*)&g_AGG[node * NCH + cb] = acc;

        atomicAdd(&sSum[cb],     acc.x); atomicAdd(&sSq[cb],     acc.x * acc.x);
        atomicAdd(&sSum[cb + 1], acc.y); atomicAdd(&sSq[cb + 1], acc.y * acc.y);
        atomicAdd(&sSum[cb + 2], acc.z); atomicAdd(&sSq[cb + 2], acc.z * acc.z);
        atomicAdd(&sSum[cb + 3], acc.w); atomicAdd(&sSq[cb + 3], acc.w * acc.w);
    }
    __syncthreads();
    if (t < 128) {
        atomicAdd(&g_bnsum[t], sSum[t]);
        atomicAdd(&g_bnsq[t],  sSq[t]);
    }
    __threadfence();
    __syncthreads();
    if (t == 0) isLast = (atomicAdd(&g_ctr, 1) == (int)gridDim.x - 1);
    __syncthreads();
    if (isLast) {
        __threadfence();
        if (t < 128) {
            float invN = 1.f / (float)N;
            float mu = g_bnsum[t] * invN;
            float var = fmaxf(g_bnsq[t] * invN - mu * mu, 0.f);
            float sc = gamma[t] * rsqrtf(var + BN_EPS);
            g_scale[t] = sc;
            g_shift[t] = beta[t] - mu * sc;
            g_bnsum[t] = 0.f;   // reset for next layer / next replay
            g_bnsq[t]  = 0.f;
        }
        if (t == 0) g_ctr = 0;
    }
}

// ---------------- final BN apply (layer 5 only) ----------------
__global__ void k_bn(const float* __restrict__ res, float* __restrict__ outp, int n4) {
    int i = blockIdx.x * blockDim.x + threadIdx.x;
    if (i >= n4) return;
    float4 v = *(const float4*)&g_AGG[i * 4];
    int c = (i * 4) & 127;
    float4 sc = *(const float4*)&g_scale[c];
    float4 sh = *(const float4*)&g_shift[c];
    v.x = fmaf(v.x, sc.x, sh.x);
    v.y = fmaf(v.y, sc.y, sh.y);
    v.z = fmaf(v.z, sc.z, sh.z);
    v.w = fmaf(v.w, sc.w, sh.w);
    if (res) {
        float4 r = *(const float4*)&res[i * 4];
        v.x += r.x; v.y += r.y; v.z += r.z; v.w += r.w;
    }
    v.x = fmaxf(v.x, 0.f); v.y = fmaxf(v.y, 0.f);
    v.z = fmaxf(v.z, 0.f); v.w = fmaxf(v.w, 0.f);
    *(float4*)&outp[i * 4] = v;
}

// ---------------- launch ----------------
extern "C" void kernel_launch(void* const* d_in, const int* in_sizes, int n_in,
                              void* d_out, int out_size) {
    const float* x      = (const float*)d_in[0];
    const int*   ei     = (const int*)d_in[1];
    const float* Ws     = (const float*)d_in[2];
    const float* atts   = (const float*)d_in[3];
    const float* attd   = (const float*)d_in[4];
    const float* biases = (const float*)d_in[5];
    const float* gammas = (const float*)d_in[6];
    const float* betas  = (const float*)d_in[7];
    float* out = (float*)d_out;

    const int N = in_sizes[0] / NCH;
    const int E = in_sizes[1] / 2;

    void* pB;
    cudaGetSymbolAddress(&pB, g_B);
    float* B = (float*)pB;

    cudaFuncSetAttribute(k_gemm_mma, cudaFuncAttributeMaxDynamicSharedMemorySize, GEMM_SMEM);

    // CSR build + W conversion (once per launch)
    k_deginit<<<(N + 255) / 256, 256>>>(N);
    k_hist<<<(E + 255) / 256, 256>>>(ei, E);
    k_scan<<<1, 1024>>>(N);
    k_scatter<<<(E + N + 255) / 256, 256>>>(ei, E, N);
    {
        dim3 g((NCH * NCH + 255) / 256, NLAYERS);
        k_wconv<<<g, 256>>>(Ws);
    }

    // per-layer GEMM load config: layer0 reads raw x; others read g_AGG+BN(prev).
    const float* xins[6] = {x, nullptr, nullptr, nullptr, nullptr, nullptr};
    const float* ress[6] = {nullptr, nullptr, nullptr, nullptr, B, nullptr};  // gemm4 adds a1
    float*       acts[6] = {nullptr, nullptr, B, nullptr, B, nullptr};        // gemm2 stores a1, gemm4 stores a3

    const int gblk = (N + 127) / 128;
    const int n4 = N * (NCH / 4);
    for (int i = 0; i < 6; i++) {
        k_gemm_mma<<<gblk, 256, GEMM_SMEM>>>(
            xins[i], ress[i], acts[i], i, atts + i * NCH, attd + i * NCH, N);
        k_agg<<<(N * 32 + 255) / 256, 256>>>(
            biases + i * NCH, gammas + i * NCH, betas + i * NCH, N);
    }
    // final: out = relu(bn5(AGG5) + a3)
    k_bn<<<(n4 + 255) / 256, 256>>>(B, out, n4);
}